// round 4
// baseline (speedup 1.0000x reference)
#include <cuda_runtime.h>
#include <cuda_bf16.h>
#include <math.h>

#define NROWS 4096
#define DIM   512
#define NCLS  128
#define MARGIN 0.3f

// Scratch (device globals: no allocation allowed)
__device__ float    g_e[NROWS * DIM];        // normalized embeddings
__device__ unsigned g_ap_bits[NROWS];        // hardest-positive dist (as uint bits, max)
__device__ unsigned g_an_bits[NROWS];        // hardest-negative dist (as uint bits, min)
__device__ int      g_cnt[NCLS];             // label histogram

// ---------------------------------------------------------------------------
// init: reset reduction buffers (graph is replayed -> must reset every launch)
// ---------------------------------------------------------------------------
__global__ void init_kernel() {
    int i = blockIdx.x * blockDim.x + threadIdx.x;
    if (i < NROWS) {
        g_ap_bits[i] = 0u;            // dist >= 0, so 0 is identity for max
        g_an_bits[i] = 0x7F800000u;   // +inf, identity for min
    }
    if (i < NCLS) g_cnt[i] = 0;
}

// ---------------------------------------------------------------------------
// normalize: one block per row, 128 threads, float4 per thread
// ---------------------------------------------------------------------------
__global__ void normalize_kernel(const float* __restrict__ emb) {
    int row = blockIdx.x;
    int t = threadIdx.x;  // 0..127
    const float4* in = (const float4*)(emb + (size_t)row * DIM);
    float4 v = in[t];
    float ss = v.x * v.x + v.y * v.y + v.z * v.z + v.w * v.w;
    #pragma unroll
    for (int o = 16; o > 0; o >>= 1) ss += __shfl_xor_sync(0xffffffffu, ss, o);
    __shared__ float sw[4];
    __shared__ float sinv;
    if ((t & 31) == 0) sw[t >> 5] = ss;
    __syncthreads();
    if (t == 0) {
        float tot = sw[0] + sw[1] + sw[2] + sw[3];
        sinv = 1.0f / fmaxf(sqrtf(tot), 1e-12f);
    }
    __syncthreads();
    float inv = sinv;
    float4 o4 = make_float4(v.x * inv, v.y * inv, v.z * inv, v.w * inv);
    ((float4*)(g_e + (size_t)row * DIM))[t] = o4;
}

// ---------------------------------------------------------------------------
// histogram of labels (int32 input — JAX downcasts int64 without x64 mode)
// ---------------------------------------------------------------------------
__global__ void hist_kernel(const int* __restrict__ labels) {
    int i = blockIdx.x * blockDim.x + threadIdx.x;
    if (i < NROWS) atomicAdd(&g_cnt[labels[i]], 1);
}

// ---------------------------------------------------------------------------
// fused gram tile + dist + masked row max/min reduction
// block = 64x64 output tile, 256 threads, 4x4 micro-tile per thread
// ---------------------------------------------------------------------------
__global__ __launch_bounds__(256, 2)
void gram_kernel(const int* __restrict__ labels) {
    __shared__ float As[16][64];
    __shared__ float Bs[16][64];
    __shared__ int sli[64];
    __shared__ int slj[64];

    const int tid = threadIdx.x;
    const int i0 = blockIdx.y * 64;
    const int j0 = blockIdx.x * 64;

    if (tid < 64)       sli[tid]      = labels[i0 + tid];
    else if (tid < 128) slj[tid - 64] = labels[j0 + (tid - 64)];

    const int lrow = tid >> 2;          // 0..63 (staging row)
    const int lk4  = (tid & 3) * 4;     // 0,4,8,12 (staging k offset)
    const float* Abase = g_e + (size_t)(i0 + lrow) * DIM + lk4;
    const float* Bbase = g_e + (size_t)(j0 + lrow) * DIM + lk4;

    const int ty = tid >> 4;            // 0..15 -> row group
    const int tx = tid & 15;            // 0..15 -> col group

    float c[4][4] = {};

    for (int k0 = 0; k0 < DIM; k0 += 16) {
        float4 av = *(const float4*)(Abase + k0);
        float4 bv = *(const float4*)(Bbase + k0);
        __syncthreads();  // previous iter's reads done (also covers sli/slj on iter 0)
        As[lk4 + 0][lrow] = av.x; As[lk4 + 1][lrow] = av.y;
        As[lk4 + 2][lrow] = av.z; As[lk4 + 3][lrow] = av.w;
        Bs[lk4 + 0][lrow] = bv.x; Bs[lk4 + 1][lrow] = bv.y;
        Bs[lk4 + 2][lrow] = bv.z; Bs[lk4 + 3][lrow] = bv.w;
        __syncthreads();
        #pragma unroll
        for (int kk = 0; kk < 16; kk++) {
            float4 a = *(const float4*)&As[kk][ty * 4];
            float4 b = *(const float4*)&Bs[kk][tx * 4];
            float ar[4] = {a.x, a.y, a.z, a.w};
            float br[4] = {b.x, b.y, b.z, b.w};
            #pragma unroll
            for (int m = 0; m < 4; m++)
                #pragma unroll
                for (int n = 0; n < 4; n++)
                    c[m][n] = fmaf(ar[m], br[n], c[m][n]);
        }
    }

    // Epilogue: dist + masks + reduce across the 16 tx lanes per row
    #pragma unroll
    for (int m = 0; m < 4; m++) {
        const int ir  = ty * 4 + m;        // local row
        const int ig  = i0 + ir;           // global row
        const int li  = sli[ir];
        float apmax = -1.0f;               // sentinel: no positive seen
        float anmin = 3.402823466e+38f;    // FLT_MAX
        #pragma unroll
        for (int n = 0; n < 4; n++) {
            const int jg = j0 + tx * 4 + n;
            const int lj = slj[tx * 4 + n];
            float sq = fmaxf(2.0f - 2.0f * c[m][n], 0.0f);
            float d = sqrtf(sq);
            bool same = (li == lj);
            if (same && (ig != jg)) apmax = fmaxf(apmax, d);
            if (!same)              anmin = fminf(anmin, d);
        }
        // butterfly reduce within the 16-lane tx group
        #pragma unroll
        for (int off = 8; off > 0; off >>= 1) {
            apmax = fmaxf(apmax, __shfl_xor_sync(0xffffffffu, apmax, off, 16));
            anmin = fminf(anmin, __shfl_xor_sync(0xffffffffu, anmin, off, 16));
        }
        if (tx == 0) {
            if (apmax >= 0.0f) atomicMax(&g_ap_bits[ig], __float_as_uint(apmax));
            atomicMin(&g_an_bits[ig], __float_as_uint(anmin));  // FLT_MAX vs +inf init: harmless
        }
    }
}

// ---------------------------------------------------------------------------
// finalize: per-row loss, validity, mean -> out[0]
// ---------------------------------------------------------------------------
__global__ void finalize_kernel(const int* __restrict__ labels,
                                float* __restrict__ out) {
    const int tid = threadIdx.x;  // 256 threads, 1 block
    float sum = 0.0f;
    int cnt = 0;
    for (int i = tid; i < NROWS; i += 256) {
        int l = labels[i];
        int c = g_cnt[l];
        if (c > 1 && c < NROWS) {   // has positive && has negative
            float ap = __uint_as_float(g_ap_bits[i]);
            float an = __uint_as_float(g_an_bits[i]);
            sum += fmaxf(ap - an + MARGIN, 0.0f);
            cnt++;
        }
    }
    __shared__ float ssum[256];
    __shared__ int   scnt[256];
    ssum[tid] = sum; scnt[tid] = cnt;
    __syncthreads();
    for (int s = 128; s > 0; s >>= 1) {
        if (tid < s) { ssum[tid] += ssum[tid + s]; scnt[tid] += scnt[tid + s]; }
        __syncthreads();
    }
    if (tid == 0) out[0] = (scnt[0] > 0) ? (ssum[0] / (float)scnt[0]) : 0.0f;
}

// ---------------------------------------------------------------------------
extern "C" void kernel_launch(void* const* d_in, const int* in_sizes, int n_in,
                              void* d_out, int out_size) {
    const float* emb = (const float*)d_in[0];
    const int* labels = (const int*)d_in[1];
    float* out = (float*)d_out;

    init_kernel<<<(NROWS + 255) / 256, 256>>>();
    normalize_kernel<<<NROWS, 128>>>(emb);
    hist_kernel<<<(NROWS + 255) / 256, 256>>>(labels);
    dim3 grid(NROWS / 64, NROWS / 64);
    gram_kernel<<<grid, 256>>>(labels);
    finalize_kernel<<<1, 256>>>(labels, out);
}

// round 5
// speedup vs baseline: 3.8545x; 3.8545x over previous
#include <cuda_runtime.h>
#include <math.h>
#include <stdint.h>

#define NROWS 4096
#define DIM   512
#define NCLS  128
#define MARGIN 0.3f
#define FLT_BIG 3.402823466e+38f

// Scratch (device globals: no allocation allowed)
__device__ float    g_e[NROWS * DIM];        // normalized, tf32-rounded embeddings
__device__ unsigned g_ap_bits[NROWS];        // hardest-positive dist (uint bits, max)
__device__ unsigned g_an_bits[NROWS];        // hardest-negative dist (uint bits, min)
__device__ int      g_cnt[NCLS];             // label histogram

// ---------------------------------------------------------------------------
__global__ void init_kernel() {
    int i = blockIdx.x * blockDim.x + threadIdx.x;
    if (i < NROWS) {
        g_ap_bits[i] = 0u;            // dist >= 0 -> 0 is identity for max
        g_an_bits[i] = 0x7F800000u;   // +inf, identity for min
    }
    if (i < NCLS) g_cnt[i] = 0;
}

// ---------------------------------------------------------------------------
// normalize + round to tf32 (so mma inputs are round-to-nearest tf32, not
// hardware truncation). One block per row, 128 threads, float4 per thread.
// ---------------------------------------------------------------------------
__device__ __forceinline__ float to_tf32(float x) {
    float r;
    asm("cvt.rna.tf32.f32 %0, %1;" : "=f"(r) : "f"(x));
    return r;
}

__global__ void normalize_kernel(const float* __restrict__ emb) {
    int row = blockIdx.x;
    int t = threadIdx.x;  // 0..127
    const float4* in = (const float4*)(emb + (size_t)row * DIM);
    float4 v = in[t];
    float ss = v.x * v.x + v.y * v.y + v.z * v.z + v.w * v.w;
    #pragma unroll
    for (int o = 16; o > 0; o >>= 1) ss += __shfl_xor_sync(0xffffffffu, ss, o);
    __shared__ float sw[4];
    __shared__ float sinv;
    if ((t & 31) == 0) sw[t >> 5] = ss;
    __syncthreads();
    if (t == 0) {
        float tot = sw[0] + sw[1] + sw[2] + sw[3];
        sinv = 1.0f / fmaxf(sqrtf(tot), 1e-12f);
    }
    __syncthreads();
    float inv = sinv;
    float4 o4 = make_float4(to_tf32(v.x * inv), to_tf32(v.y * inv),
                            to_tf32(v.z * inv), to_tf32(v.w * inv));
    ((float4*)(g_e + (size_t)row * DIM))[t] = o4;
}

// ---------------------------------------------------------------------------
__global__ void hist_kernel(const int* __restrict__ labels) {
    int i = blockIdx.x * blockDim.x + threadIdx.x;
    if (i < NROWS) atomicAdd(&g_cnt[labels[i]], 1);
}

// ---------------------------------------------------------------------------
// Tensor-core gram tile + fused dist/mask/row-reduction epilogue.
// Block tile 128x128, BK=32, 256 threads = 8 warps (2 x 4) of 64x32 warp tiles.
// mma.sync m16n8k8 tf32, fp32 accumulate.
// ---------------------------------------------------------------------------
#define BM 128
#define BN 128
#define BK 32
#define SST 36   // smem row stride (floats): bank = (4g+t) -> conflict-free frags

#define MMA_TF32(cc, aa, bb)                                                   \
    asm volatile(                                                              \
        "mma.sync.aligned.m16n8k8.row.col.f32.tf32.tf32.f32 "                  \
        "{%0,%1,%2,%3}, {%4,%5,%6,%7}, {%8,%9}, {%0,%1,%2,%3};"                \
        : "+f"((cc)[0]), "+f"((cc)[1]), "+f"((cc)[2]), "+f"((cc)[3])           \
        : "r"((aa)[0]), "r"((aa)[1]), "r"((aa)[2]), "r"((aa)[3]),              \
          "r"((bb)[0]), "r"((bb)[1]))

__global__ __launch_bounds__(256, 2)
void gram_tc_kernel(const int* __restrict__ labels) {
    __shared__ float As[BM][SST];
    __shared__ float Bs[BN][SST];
    __shared__ int sli[BM];
    __shared__ int slj[BN];

    const int tid = threadIdx.x;
    const int i0 = blockIdx.y * BM;
    const int j0 = blockIdx.x * BN;

    if (tid < 128) sli[tid] = labels[i0 + tid];
    else           slj[tid - 128] = labels[j0 + (tid - 128)];

    const int warp = tid >> 5;
    const int lane = tid & 31;
    const int wm = warp >> 2;      // 0..1 -> 64-row band
    const int wn = warp & 3;       // 0..3 -> 32-col band
    const int g  = lane >> 2;      // groupID 0..7
    const int t  = lane & 3;       // threadID-in-group 0..3

    // staging map: each thread stores 4 float4 per tile per operand
    const int lrow = tid >> 3;           // 0..31
    const int lc4  = (tid & 7) * 4;      // 0,4,...,28
    const float* Ag = g_e + (size_t)(i0 + lrow) * DIM + lc4;
    const float* Bg = g_e + (size_t)(j0 + lrow) * DIM + lc4;

    float c[4][4][4];
    #pragma unroll
    for (int mt = 0; mt < 4; mt++)
        #pragma unroll
        for (int nt = 0; nt < 4; nt++)
            #pragma unroll
            for (int e = 0; e < 4; e++) c[mt][nt][e] = 0.0f;

    for (int kc = 0; kc < DIM; kc += BK) {
        __syncthreads();   // previous iteration's readers are done
        #pragma unroll
        for (int i = 0; i < 4; i++) {
            float4 av = *(const float4*)(Ag + (size_t)(i * 32) * DIM + kc);
            float4 bv = *(const float4*)(Bg + (size_t)(i * 32) * DIM + kc);
            *(float4*)&As[lrow + 32 * i][lc4] = av;
            *(float4*)&Bs[lrow + 32 * i][lc4] = bv;
        }
        __syncthreads();

        #pragma unroll
        for (int ks = 0; ks < 4; ks++) {
            const int kb = ks * 8;
            uint32_t a[4][4], b[4][2];
            #pragma unroll
            for (int mt = 0; mt < 4; mt++) {
                const int r = wm * 64 + mt * 16 + g;
                a[mt][0] = __float_as_uint(As[r    ][kb + t    ]);
                a[mt][1] = __float_as_uint(As[r + 8][kb + t    ]);
                a[mt][2] = __float_as_uint(As[r    ][kb + t + 4]);
                a[mt][3] = __float_as_uint(As[r + 8][kb + t + 4]);
            }
            #pragma unroll
            for (int nt = 0; nt < 4; nt++) {
                const int rn = wn * 32 + nt * 8 + g;
                b[nt][0] = __float_as_uint(Bs[rn][kb + t    ]);
                b[nt][1] = __float_as_uint(Bs[rn][kb + t + 4]);
            }
            #pragma unroll
            for (int mt = 0; mt < 4; mt++)
                #pragma unroll
                for (int nt = 0; nt < 4; nt++)
                    MMA_TF32(c[mt][nt], a[mt], b[nt]);
        }
    }

    // Epilogue. C frag layout: c0,c1 -> row g,   cols 2t,2t+1
    //                          c2,c3 -> row g+8, cols 2t,2t+1
    #pragma unroll
    for (int mt = 0; mt < 4; mt++) {
        const int lr0 = wm * 64 + mt * 16 + g;
        const int lr1 = lr0 + 8;
        const int ig0 = i0 + lr0, ig1 = i0 + lr1;
        const int li0 = sli[lr0], li1 = sli[lr1];
        float ap0 = -1.0f, an0 = FLT_BIG;
        float ap1 = -1.0f, an1 = FLT_BIG;
        #pragma unroll
        for (int nt = 0; nt < 4; nt++) {
            #pragma unroll
            for (int e = 0; e < 2; e++) {
                const int ljl = wn * 32 + nt * 8 + 2 * t + e;
                const int jg = j0 + ljl;
                const int lj = slj[ljl];
                float d0 = sqrtf(fmaxf(2.0f - 2.0f * c[mt][nt][e],     0.0f));
                float d1 = sqrtf(fmaxf(2.0f - 2.0f * c[mt][nt][2 + e], 0.0f));
                if (li0 == lj) { if (ig0 != jg) ap0 = fmaxf(ap0, d0); }
                else           an0 = fminf(an0, d0);
                if (li1 == lj) { if (ig1 != jg) ap1 = fmaxf(ap1, d1); }
                else           an1 = fminf(an1, d1);
            }
        }
        // reduce over the 4 t-lanes (lanes 4g..4g+3)
        #pragma unroll
        for (int off = 1; off < 4; off <<= 1) {
            ap0 = fmaxf(ap0, __shfl_xor_sync(0xffffffffu, ap0, off, 4));
            an0 = fminf(an0, __shfl_xor_sync(0xffffffffu, an0, off, 4));
            ap1 = fmaxf(ap1, __shfl_xor_sync(0xffffffffu, ap1, off, 4));
            an1 = fminf(an1, __shfl_xor_sync(0xffffffffu, an1, off, 4));
        }
        if (t == 0) {
            if (ap0 >= 0.0f) atomicMax(&g_ap_bits[ig0], __float_as_uint(ap0));
            atomicMin(&g_an_bits[ig0], __float_as_uint(an0));
            if (ap1 >= 0.0f) atomicMax(&g_ap_bits[ig1], __float_as_uint(ap1));
            atomicMin(&g_an_bits[ig1], __float_as_uint(an1));
        }
    }
}

// ---------------------------------------------------------------------------
__global__ void finalize_kernel(const int* __restrict__ labels,
                                float* __restrict__ out) {
    const int tid = threadIdx.x;  // 256 threads, 1 block
    float sum = 0.0f;
    int cnt = 0;
    for (int i = tid; i < NROWS; i += 256) {
        int l = labels[i];
        int c = g_cnt[l];
        if (c > 1 && c < NROWS) {   // has positive && has negative
            float ap = __uint_as_float(g_ap_bits[i]);
            float an = __uint_as_float(g_an_bits[i]);
            sum += fmaxf(ap - an + MARGIN, 0.0f);
            cnt++;
        }
    }
    __shared__ float ssum[256];
    __shared__ int   scnt[256];
    ssum[tid] = sum; scnt[tid] = cnt;
    __syncthreads();
    for (int s = 128; s > 0; s >>= 1) {
        if (tid < s) { ssum[tid] += ssum[tid + s]; scnt[tid] += scnt[tid + s]; }
        __syncthreads();
    }
    if (tid == 0) out[0] = (scnt[0] > 0) ? (ssum[0] / (float)scnt[0]) : 0.0f;
}

// ---------------------------------------------------------------------------
extern "C" void kernel_launch(void* const* d_in, const int* in_sizes, int n_in,
                              void* d_out, int out_size) {
    const float* emb = (const float*)d_in[0];
    const int* labels = (const int*)d_in[1];
    float* out = (float*)d_out;

    init_kernel<<<(NROWS + 255) / 256, 256>>>();
    normalize_kernel<<<NROWS, 128>>>(emb);
    hist_kernel<<<(NROWS + 255) / 256, 256>>>(labels);
    dim3 grid(NROWS / BN, NROWS / BM);
    gram_tc_kernel<<<grid, 256>>>(labels);
    finalize_kernel<<<1, 256>>>(labels, out);
}

// round 6
// speedup vs baseline: 5.7219x; 1.4845x over previous
#include <cuda_runtime.h>
#include <math.h>
#include <stdint.h>

#define NROWS 4096
#define DIM   512
#define NCLS  128
#define MARGIN 0.3f
#define FLT_BIG 3.402823466e+38f

#define BM 128
#define BN 128
#define BK 32
#define SST 36          // smem row stride (floats): conflict-free frag reads
#define NTILE (NROWS / BM)              // 32
#define NTRI  (NTILE * (NTILE + 1) / 2) // 528 upper-triangular tiles

// Scratch (device globals: no allocation allowed)
__device__ float    g_e[NROWS * DIM];        // normalized, tf32-rounded embeddings
__device__ unsigned g_ap_bits[NROWS];        // hardest-positive dist (uint bits, max)
__device__ unsigned g_an_bits[NROWS];        // hardest-negative dist (uint bits, min)
__device__ int      g_cnt[NCLS];             // label histogram

// ---------------------------------------------------------------------------
// init: reset class histogram only (row stats are reset inside normalize)
// ---------------------------------------------------------------------------
__global__ void init_kernel() {
    int i = threadIdx.x;
    if (i < NCLS) g_cnt[i] = 0;
}

// ---------------------------------------------------------------------------
// normalize + tf32 round + fused hist + per-row reduction-buffer reset.
// One block per row, 128 threads, float4 per thread.
// ---------------------------------------------------------------------------
__device__ __forceinline__ float to_tf32(float x) {
    float r;
    asm("cvt.rna.tf32.f32 %0, %1;" : "=f"(r) : "f"(x));
    return r;
}

__global__ void normalize_kernel(const float* __restrict__ emb,
                                 const int* __restrict__ labels) {
    int row = blockIdx.x;
    int t = threadIdx.x;  // 0..127
    if (t == 0) {
        atomicAdd(&g_cnt[labels[row]], 1);
        g_ap_bits[row] = 0u;            // dist >= 0 -> 0 is identity for max
        g_an_bits[row] = 0x7F800000u;   // +inf, identity for min
    }
    const float4* in = (const float4*)(emb + (size_t)row * DIM);
    float4 v = in[t];
    float ss = v.x * v.x + v.y * v.y + v.z * v.z + v.w * v.w;
    #pragma unroll
    for (int o = 16; o > 0; o >>= 1) ss += __shfl_xor_sync(0xffffffffu, ss, o);
    __shared__ float sw[4];
    __shared__ float sinv;
    if ((t & 31) == 0) sw[t >> 5] = ss;
    __syncthreads();
    if (t == 0) {
        float tot = sw[0] + sw[1] + sw[2] + sw[3];
        sinv = 1.0f / fmaxf(sqrtf(tot), 1e-12f);
    }
    __syncthreads();
    float inv = sinv;
    float4 o4 = make_float4(to_tf32(v.x * inv), to_tf32(v.y * inv),
                            to_tf32(v.z * inv), to_tf32(v.w * inv));
    ((float4*)(g_e + (size_t)row * DIM))[t] = o4;
}

// ---------------------------------------------------------------------------
// Tensor-core gram: upper-triangular tiles only. Dual-axis epilogue:
//   row pass   -> stats for rows i (all tiles)
//   column pass-> stats for rows j via symmetry (off-diagonal tiles only)
// 128x128 tile, BK=32, 256 threads = 8 warps (2 x 4) of 64x32 warp tiles.
// ---------------------------------------------------------------------------
#define MMA_TF32(cc, aa, bb)                                                   \
    asm volatile(                                                              \
        "mma.sync.aligned.m16n8k8.row.col.f32.tf32.tf32.f32 "                  \
        "{%0,%1,%2,%3}, {%4,%5,%6,%7}, {%8,%9}, {%0,%1,%2,%3};"                \
        : "+f"((cc)[0]), "+f"((cc)[1]), "+f"((cc)[2]), "+f"((cc)[3])           \
        : "r"((aa)[0]), "r"((aa)[1]), "r"((aa)[2]), "r"((aa)[3]),              \
          "r"((bb)[0]), "r"((bb)[1]))

__device__ __forceinline__ int tri_offset(int bi) {
    return bi * NTILE - bi * (bi - 1) / 2;   // # tiles with first index < bi
}

__global__ __launch_bounds__(256, 2)
void gram_tc_kernel(const int* __restrict__ labels) {
    __shared__ float As[BM][SST];
    __shared__ float Bs[BN][SST];
    __shared__ int sli[BM];
    __shared__ int slj[BN];

    // decode linear tile id -> (bi, bj) with bi <= bj
    const int u = blockIdx.x;
    int bi = (int)((65.0f - sqrtf(65.0f * 65.0f - 8.0f * (float)u)) * 0.5f);
    while (tri_offset(bi) > u) bi--;
    while (tri_offset(bi + 1) <= u) bi++;
    const int bj = bi + (u - tri_offset(bi));

    const int tid = threadIdx.x;
    const int i0 = bi * BM;
    const int j0 = bj * BN;
    const bool offdiag = (bi != bj);

    if (tid < 128) sli[tid] = labels[i0 + tid];
    else           slj[tid - 128] = labels[j0 + (tid - 128)];

    const int warp = tid >> 5;
    const int lane = tid & 31;
    const int wm = warp >> 2;      // 0..1 -> 64-row band
    const int wn = warp & 3;       // 0..3 -> 32-col band
    const int g  = lane >> 2;      // groupID 0..7
    const int t  = lane & 3;       // threadID-in-group 0..3

    const int lrow = tid >> 3;           // 0..31
    const int lc4  = (tid & 7) * 4;      // 0,4,...,28
    const float* Ag = g_e + (size_t)(i0 + lrow) * DIM + lc4;
    const float* Bg = g_e + (size_t)(j0 + lrow) * DIM + lc4;

    float c[4][4][4];
    #pragma unroll
    for (int mt = 0; mt < 4; mt++)
        #pragma unroll
        for (int nt = 0; nt < 4; nt++)
            #pragma unroll
            for (int e = 0; e < 4; e++) c[mt][nt][e] = 0.0f;

    for (int kc = 0; kc < DIM; kc += BK) {
        __syncthreads();   // previous iteration's readers done (covers sli/slj @ iter 0)
        #pragma unroll
        for (int i = 0; i < 4; i++) {
            float4 av = *(const float4*)(Ag + (size_t)(i * 32) * DIM + kc);
            float4 bv = *(const float4*)(Bg + (size_t)(i * 32) * DIM + kc);
            *(float4*)&As[lrow + 32 * i][lc4] = av;
            *(float4*)&Bs[lrow + 32 * i][lc4] = bv;
        }
        __syncthreads();

        #pragma unroll
        for (int ks = 0; ks < 4; ks++) {
            const int kb = ks * 8;
            uint32_t a[4][4], b[4][2];
            #pragma unroll
            for (int mt = 0; mt < 4; mt++) {
                const int r = wm * 64 + mt * 16 + g;
                a[mt][0] = __float_as_uint(As[r    ][kb + t    ]);
                a[mt][1] = __float_as_uint(As[r + 8][kb + t    ]);
                a[mt][2] = __float_as_uint(As[r    ][kb + t + 4]);
                a[mt][3] = __float_as_uint(As[r + 8][kb + t + 4]);
            }
            #pragma unroll
            for (int nt = 0; nt < 4; nt++) {
                const int rn = wn * 32 + nt * 8 + g;
                b[nt][0] = __float_as_uint(Bs[rn][kb + t    ]);
                b[nt][1] = __float_as_uint(Bs[rn][kb + t + 4]);
            }
            #pragma unroll
            for (int mt = 0; mt < 4; mt++)
                #pragma unroll
                for (int nt = 0; nt < 4; nt++)
                    MMA_TF32(c[mt][nt], a[mt], b[nt]);
        }
    }

    // -------- epilogue --------
    // Convert accumulators to distances in place.
    // C frag layout: e=0,1 -> row g,   cols 2t,2t+1
    //               e=2,3 -> row g+8, cols 2t,2t+1
    #pragma unroll
    for (int mt = 0; mt < 4; mt++)
        #pragma unroll
        for (int nt = 0; nt < 4; nt++)
            #pragma unroll
            for (int e = 0; e < 4; e++)
                c[mt][nt][e] = sqrtf(fmaxf(2.0f - 2.0f * c[mt][nt][e], 0.0f));

    // Row pass: stats for rows i
    #pragma unroll
    for (int mt = 0; mt < 4; mt++) {
        const int lr0 = wm * 64 + mt * 16 + g;
        const int lr1 = lr0 + 8;
        const int ig0 = i0 + lr0, ig1 = i0 + lr1;
        const int li0 = sli[lr0], li1 = sli[lr1];
        float ap0 = -1.0f, an0 = FLT_BIG;
        float ap1 = -1.0f, an1 = FLT_BIG;
        #pragma unroll
        for (int nt = 0; nt < 4; nt++) {
            #pragma unroll
            for (int e = 0; e < 2; e++) {
                const int ljl = wn * 32 + nt * 8 + 2 * t + e;
                const int jg = j0 + ljl;
                const int lj = slj[ljl];
                float d0 = c[mt][nt][e];
                float d1 = c[mt][nt][2 + e];
                if (li0 == lj) { if (ig0 != jg) ap0 = fmaxf(ap0, d0); }
                else           an0 = fminf(an0, d0);
                if (li1 == lj) { if (ig1 != jg) ap1 = fmaxf(ap1, d1); }
                else           an1 = fminf(an1, d1);
            }
        }
        #pragma unroll
        for (int off = 1; off < 4; off <<= 1) {
            ap0 = fmaxf(ap0, __shfl_xor_sync(0xffffffffu, ap0, off, 4));
            an0 = fminf(an0, __shfl_xor_sync(0xffffffffu, an0, off, 4));
            ap1 = fmaxf(ap1, __shfl_xor_sync(0xffffffffu, ap1, off, 4));
            an1 = fminf(an1, __shfl_xor_sync(0xffffffffu, an1, off, 4));
        }
        if (t == 0) {
            if (ap0 >= 0.0f) atomicMax(&g_ap_bits[ig0], __float_as_uint(ap0));
            atomicMin(&g_an_bits[ig0], __float_as_uint(an0));
            if (ap1 >= 0.0f) atomicMax(&g_ap_bits[ig1], __float_as_uint(ap1));
            atomicMin(&g_an_bits[ig1], __float_as_uint(an1));
        }
    }

    // Column pass: by symmetry d(j,i)=d(i,j) -> stats for rows j.
    // Off-diagonal tiles only (diagonal block is symmetric: row pass complete;
    // i/j ranges disjoint here so no self-pair exclusion needed).
    if (offdiag) {
        #pragma unroll
        for (int nt = 0; nt < 4; nt++) {
            #pragma unroll
            for (int e = 0; e < 2; e++) {
                const int ljl = wn * 32 + nt * 8 + 2 * t + e;
                const int lj = slj[ljl];
                float cap = -1.0f, can = FLT_BIG;
                #pragma unroll
                for (int mt = 0; mt < 4; mt++) {
                    const int lr0 = wm * 64 + mt * 16 + g;
                    const int li0 = sli[lr0], li1 = sli[lr0 + 8];
                    float d0 = c[mt][nt][e];
                    float d1 = c[mt][nt][2 + e];
                    if (li0 == lj) cap = fmaxf(cap, d0); else can = fminf(can, d0);
                    if (li1 == lj) cap = fmaxf(cap, d1); else can = fminf(can, d1);
                }
                // reduce across the 8 g-groups (lanes 4g + t)
                #pragma unroll
                for (int off = 4; off < 32; off <<= 1) {
                    cap = fmaxf(cap, __shfl_xor_sync(0xffffffffu, cap, off, 32));
                    can = fminf(can, __shfl_xor_sync(0xffffffffu, can, off, 32));
                }
                if (lane < 4) {   // g == 0 lanes hold the result
                    const int jg = j0 + ljl;
                    if (cap >= 0.0f) atomicMax(&g_ap_bits[jg], __float_as_uint(cap));
                    atomicMin(&g_an_bits[jg], __float_as_uint(can));
                }
            }
        }
    }
}

// ---------------------------------------------------------------------------
__global__ void finalize_kernel(const int* __restrict__ labels,
                                float* __restrict__ out) {
    const int tid = threadIdx.x;  // 256 threads, 1 block
    float sum = 0.0f;
    int cnt = 0;
    for (int i = tid; i < NROWS; i += 256) {
        int l = labels[i];
        int c = g_cnt[l];
        if (c > 1 && c < NROWS) {   // has positive && has negative
            float ap = __uint_as_float(g_ap_bits[i]);
            float an = __uint_as_float(g_an_bits[i]);
            sum += fmaxf(ap - an + MARGIN, 0.0f);
            cnt++;
        }
    }
    __shared__ float ssum[256];
    __shared__ int   scnt[256];
    ssum[tid] = sum; scnt[tid] = cnt;
    __syncthreads();
    for (int s = 128; s > 0; s >>= 1) {
        if (tid < s) { ssum[tid] += ssum[tid + s]; scnt[tid] += scnt[tid + s]; }
        __syncthreads();
    }
    if (tid == 0) out[0] = (scnt[0] > 0) ? (ssum[0] / (float)scnt[0]) : 0.0f;
}

// ---------------------------------------------------------------------------
extern "C" void kernel_launch(void* const* d_in, const int* in_sizes, int n_in,
                              void* d_out, int out_size) {
    const float* emb = (const float*)d_in[0];
    const int* labels = (const int*)d_in[1];
    float* out = (float*)d_out;

    init_kernel<<<1, 128>>>();
    normalize_kernel<<<NROWS, 128>>>(emb, labels);
    gram_tc_kernel<<<NTRI, 256>>>(labels);
    finalize_kernel<<<1, 256>>>(labels, out);
}

// round 7
// speedup vs baseline: 5.8969x; 1.0306x over previous
#include <cuda_runtime.h>
#include <math.h>
#include <stdint.h>

#define NROWS 4096
#define DIM   512
#define NCLS  128
#define MARGIN 0.3f
#define FLT_BIG 3.402823466e+38f

#define BM 128
#define BN 128
#define BK 16
#define SST 20          // smem row stride (floats): bank = g*20+t hits all 32 banks
#define NCH (DIM / BK)  // 32 k-chunks
#define NTILE (NROWS / BM)              // 32
#define NTRI  (NTILE * (NTILE + 1) / 2) // 528 upper-triangular tiles
#define NFB 16          // finalize partial blocks

// Scratch (device globals: no allocation allowed)
__device__ float    g_e[NROWS * DIM];   // normalized, tf32-rounded embeddings
__device__ unsigned g_ap_bits[NROWS];   // min-gram-over-positives (monotone uint key)
__device__ unsigned g_an_bits[NROWS];   // max-gram-over-negatives (monotone uint key)
__device__ int      g_cnt[NCLS];        // label histogram
__device__ float    g_psum[NFB];
__device__ int      g_pcnt[NFB];

// monotone float <-> uint key (order-preserving for all finite floats)
__device__ __forceinline__ unsigned fkey(float x) {
    unsigned b = __float_as_uint(x);
    return (b & 0x80000000u) ? ~b : (b | 0x80000000u);
}
__device__ __forceinline__ float funkey(unsigned k) {
    unsigned b = (k & 0x80000000u) ? (k ^ 0x80000000u) : ~k;
    return __uint_as_float(b);
}

// ---------------------------------------------------------------------------
__global__ void init_kernel() {
    int i = threadIdx.x;
    if (i < NCLS) g_cnt[i] = 0;
}

// ---------------------------------------------------------------------------
// normalize + tf32 round + fused hist + per-row reduction-buffer reset.
// ---------------------------------------------------------------------------
__device__ __forceinline__ float to_tf32(float x) {
    float r;
    asm("cvt.rna.tf32.f32 %0, %1;" : "=f"(r) : "f"(x));
    return r;
}

__global__ void normalize_kernel(const float* __restrict__ emb,
                                 const int* __restrict__ labels) {
    int row = blockIdx.x;
    int t = threadIdx.x;  // 0..127
    if (t == 0) {
        atomicAdd(&g_cnt[labels[row]], 1);
        g_ap_bits[row] = 0xFFFFFFFFu;   // identity for key-min
        g_an_bits[row] = 0u;            // identity for key-max
    }
    const float4* in = (const float4*)(emb + (size_t)row * DIM);
    float4 v = in[t];
    float ss = v.x * v.x + v.y * v.y + v.z * v.z + v.w * v.w;
    #pragma unroll
    for (int o = 16; o > 0; o >>= 1) ss += __shfl_xor_sync(0xffffffffu, ss, o);
    __shared__ float sw[4];
    __shared__ float sinv;
    if ((t & 31) == 0) sw[t >> 5] = ss;
    __syncthreads();
    if (t == 0) {
        float tot = sw[0] + sw[1] + sw[2] + sw[3];
        sinv = 1.0f / fmaxf(sqrtf(tot), 1e-12f);
    }
    __syncthreads();
    float inv = sinv;
    float4 o4 = make_float4(to_tf32(v.x * inv), to_tf32(v.y * inv),
                            to_tf32(v.z * inv), to_tf32(v.w * inv));
    ((float4*)(g_e + (size_t)row * DIM))[t] = o4;
}

// ---------------------------------------------------------------------------
// Tensor-core gram, upper-triangular tiles, cp.async 2-stage pipeline,
// gram-space dual-axis epilogue (hardest-pos = min gram, hardest-neg = max).
// ---------------------------------------------------------------------------
#define MMA_TF32(cc, aa, bb)                                                   \
    asm volatile(                                                              \
        "mma.sync.aligned.m16n8k8.row.col.f32.tf32.tf32.f32 "                  \
        "{%0,%1,%2,%3}, {%4,%5,%6,%7}, {%8,%9}, {%0,%1,%2,%3};"                \
        : "+f"((cc)[0]), "+f"((cc)[1]), "+f"((cc)[2]), "+f"((cc)[3])           \
        : "r"((aa)[0]), "r"((aa)[1]), "r"((aa)[2]), "r"((aa)[3]),              \
          "r"((bb)[0]), "r"((bb)[1]))

#define CP16(dst, src)                                                         \
    asm volatile("cp.async.cg.shared.global [%0], [%1], 16;"                   \
                 :: "r"(dst), "l"(src))
#define CP_COMMIT() asm volatile("cp.async.commit_group;")
#define CP_WAIT1()  asm volatile("cp.async.wait_group 1;")
#define CP_WAIT0()  asm volatile("cp.async.wait_group 0;")

__device__ __forceinline__ int tri_offset(int bi) {
    return bi * NTILE - bi * (bi - 1) / 2;
}

__global__ __launch_bounds__(256, 2)
void gram_tc_kernel(const int* __restrict__ labels) {
    __shared__ float As[2][BM][SST];
    __shared__ float Bs[2][BN][SST];
    __shared__ int sli[BM];
    __shared__ int slj[BN];

    // decode linear tile id -> (bi, bj), bi <= bj
    const int u = blockIdx.x;
    int bi = (int)((65.0f - sqrtf(65.0f * 65.0f - 8.0f * (float)u)) * 0.5f);
    while (tri_offset(bi) > u) bi--;
    while (tri_offset(bi + 1) <= u) bi++;
    const int bj = bi + (u - tri_offset(bi));

    const int tid = threadIdx.x;
    const int i0 = bi * BM;
    const int j0 = bj * BN;
    const bool offdiag = (bi != bj);

    if (tid < 128) sli[tid] = labels[i0 + tid];
    else           slj[tid - 128] = labels[j0 + (tid - 128)];

    const int warp = tid >> 5;
    const int lane = tid & 31;
    const int wm = warp >> 2;      // 0..1 -> 64-row band
    const int wn = warp & 3;       // 0..3 -> 32-col band
    const int g  = lane >> 2;      // 0..7
    const int t  = lane & 3;       // 0..3

    // staging map: thread covers rows {r, r+64}, 16B (4 floats) at col c4
    const int r  = tid >> 2;       // 0..63
    const int c4 = (tid & 3) * 4;  // 0,4,8,12
    const float* gA0 = g_e + (size_t)(i0 + r) * DIM + c4;
    const float* gA1 = gA0 + (size_t)64 * DIM;
    const float* gB0 = g_e + (size_t)(j0 + r) * DIM + c4;
    const float* gB1 = gB0 + (size_t)64 * DIM;

    uint32_t sA, sB;
    {
        uint32_t a;
        asm("{ .reg .u64 x; cvta.to.shared.u64 x, %1; cvt.u32.u64 %0, x; }"
            : "=r"(a) : "l"(&As[0][0][0]));
        sA = a + (uint32_t)(r * SST + c4) * 4u;
        asm("{ .reg .u64 x; cvta.to.shared.u64 x, %1; cvt.u32.u64 %0, x; }"
            : "=r"(a) : "l"(&Bs[0][0][0]));
        sB = a + (uint32_t)(r * SST + c4) * 4u;
    }
    const uint32_t STAGE = (uint32_t)(BM * SST) * 4u;   // bytes per stage
    const uint32_t HALF  = (uint32_t)(64 * SST) * 4u;   // +64 rows

    float c[4][4][4];
    #pragma unroll
    for (int mt = 0; mt < 4; mt++)
        #pragma unroll
        for (int nt = 0; nt < 4; nt++)
            #pragma unroll
            for (int e = 0; e < 4; e++) c[mt][nt][e] = 0.0f;

    // prologue: prefetch chunk 0 into stage 0
    CP16(sA,        gA0);  CP16(sA + HALF,        gA1);
    CP16(sB,        gB0);  CP16(sB + HALF,        gB1);
    CP_COMMIT();

    for (int ch = 0; ch < NCH; ch++) {
        const int s = ch & 1;
        if (ch + 1 < NCH) {
            const uint32_t so = ((ch + 1) & 1) ? STAGE : 0u;
            const int kc = (ch + 1) * BK;
            CP16(sA + so,        gA0 + kc);  CP16(sA + so + HALF, gA1 + kc);
            CP16(sB + so,        gB0 + kc);  CP16(sB + so + HALF, gB1 + kc);
            CP_COMMIT();
            CP_WAIT1();
        } else {
            CP_WAIT0();
        }
        __syncthreads();

        #pragma unroll
        for (int ks = 0; ks < 2; ks++) {
            const int kb = ks * 8;
            uint32_t a[4][4], b[4][2];
            #pragma unroll
            for (int mt = 0; mt < 4; mt++) {
                const int rr = wm * 64 + mt * 16 + g;
                a[mt][0] = __float_as_uint(As[s][rr    ][kb + t    ]);
                a[mt][1] = __float_as_uint(As[s][rr + 8][kb + t    ]);
                a[mt][2] = __float_as_uint(As[s][rr    ][kb + t + 4]);
                a[mt][3] = __float_as_uint(As[s][rr + 8][kb + t + 4]);
            }
            #pragma unroll
            for (int nt = 0; nt < 4; nt++) {
                const int rn = wn * 32 + nt * 8 + g;
                b[nt][0] = __float_as_uint(Bs[s][rn][kb + t    ]);
                b[nt][1] = __float_as_uint(Bs[s][rn][kb + t + 4]);
            }
            #pragma unroll
            for (int mt = 0; mt < 4; mt++)
                #pragma unroll
                for (int nt = 0; nt < 4; nt++)
                    MMA_TF32(c[mt][nt], a[mt], b[nt]);
        }
        __syncthreads();
    }

    // -------- epilogue (gram space: pos -> min gram, neg -> max gram) --------
    // C frag layout: e=0,1 -> row g,   cols 2t,2t+1 ; e=2,3 -> row g+8
    #pragma unroll
    for (int mt = 0; mt < 4; mt++) {
        const int lr0 = wm * 64 + mt * 16 + g;
        const int lr1 = lr0 + 8;
        const int ig0 = i0 + lr0, ig1 = i0 + lr1;
        const int li0 = sli[lr0], li1 = sli[lr1];
        float gp0 = FLT_BIG, gn0 = -FLT_BIG;   // pos-min, neg-max for row ig0
        float gp1 = FLT_BIG, gn1 = -FLT_BIG;
        #pragma unroll
        for (int nt = 0; nt < 4; nt++) {
            #pragma unroll
            for (int e = 0; e < 2; e++) {
                const int ljl = wn * 32 + nt * 8 + 2 * t + e;
                const int jg = j0 + ljl;
                const int lj = slj[ljl];
                float v0 = c[mt][nt][e];
                float v1 = c[mt][nt][2 + e];
                if (li0 == lj) { if (ig0 != jg) gp0 = fminf(gp0, v0); }
                else           gn0 = fmaxf(gn0, v0);
                if (li1 == lj) { if (ig1 != jg) gp1 = fminf(gp1, v1); }
                else           gn1 = fmaxf(gn1, v1);
            }
        }
        #pragma unroll
        for (int off = 1; off < 4; off <<= 1) {
            gp0 = fminf(gp0, __shfl_xor_sync(0xffffffffu, gp0, off, 4));
            gn0 = fmaxf(gn0, __shfl_xor_sync(0xffffffffu, gn0, off, 4));
            gp1 = fminf(gp1, __shfl_xor_sync(0xffffffffu, gp1, off, 4));
            gn1 = fmaxf(gn1, __shfl_xor_sync(0xffffffffu, gn1, off, 4));
        }
        if (t == 0) {
            if (gp0 <  FLT_BIG) atomicMin(&g_ap_bits[ig0], fkey(gp0));
            if (gn0 > -FLT_BIG) atomicMax(&g_an_bits[ig0], fkey(gn0));
            if (gp1 <  FLT_BIG) atomicMin(&g_ap_bits[ig1], fkey(gp1));
            if (gn1 > -FLT_BIG) atomicMax(&g_an_bits[ig1], fkey(gn1));
        }
    }

    // Column pass via symmetry (off-diagonal tiles; i/j ranges disjoint)
    if (offdiag) {
        #pragma unroll
        for (int nt = 0; nt < 4; nt++) {
            #pragma unroll
            for (int e = 0; e < 2; e++) {
                const int ljl = wn * 32 + nt * 8 + 2 * t + e;
                const int lj = slj[ljl];
                float gp = FLT_BIG, gn = -FLT_BIG;
                #pragma unroll
                for (int mt = 0; mt < 4; mt++) {
                    const int lr0 = wm * 64 + mt * 16 + g;
                    const int li0 = sli[lr0], li1 = sli[lr0 + 8];
                    float v0 = c[mt][nt][e];
                    float v1 = c[mt][nt][2 + e];
                    if (li0 == lj) gp = fminf(gp, v0); else gn = fmaxf(gn, v0);
                    if (li1 == lj) gp = fminf(gp, v1); else gn = fmaxf(gn, v1);
                }
                #pragma unroll
                for (int off = 4; off < 32; off <<= 1) {
                    gp = fminf(gp, __shfl_xor_sync(0xffffffffu, gp, off, 32));
                    gn = fmaxf(gn, __shfl_xor_sync(0xffffffffu, gn, off, 32));
                }
                if (lane < 4) {   // g == 0 lanes hold the result
                    const int jg = j0 + ljl;
                    if (gp <  FLT_BIG) atomicMin(&g_ap_bits[jg], fkey(gp));
                    if (gn > -FLT_BIG) atomicMax(&g_an_bits[jg], fkey(gn));
                }
            }
        }
    }
}

// ---------------------------------------------------------------------------
// finalize stage 1: 16 blocks x 256 threads, 1 row/thread, deterministic
// per-block partials into fixed slots.
// ---------------------------------------------------------------------------
__global__ void finalize1_kernel(const int* __restrict__ labels) {
    const int tid = threadIdx.x;
    const int i = blockIdx.x * 256 + tid;
    int l = labels[i];
    int cc = g_cnt[l];
    float loss = 0.0f;
    int valid = 0;
    if (cc > 1 && cc < NROWS) {
        float gmin = funkey(g_ap_bits[i]);   // min gram over positives
        float gmax = funkey(g_an_bits[i]);   // max gram over negatives
        float ap = sqrtf(fmaxf(2.0f - 2.0f * gmin, 0.0f));
        float an = sqrtf(fmaxf(2.0f - 2.0f * gmax, 0.0f));
        loss = fmaxf(ap - an + MARGIN, 0.0f);
        valid = 1;
    }
    __shared__ float ssum[256];
    __shared__ int   scnt[256];
    ssum[tid] = loss; scnt[tid] = valid;
    __syncthreads();
    for (int s = 128; s > 0; s >>= 1) {
        if (tid < s) { ssum[tid] += ssum[tid + s]; scnt[tid] += scnt[tid + s]; }
        __syncthreads();
    }
    if (tid == 0) { g_psum[blockIdx.x] = ssum[0]; g_pcnt[blockIdx.x] = scnt[0]; }
}

__global__ void finalize2_kernel(float* __restrict__ out) {
    float s = 0.0f;
    int c = 0;
    #pragma unroll
    for (int i = 0; i < NFB; i++) { s += g_psum[i]; c += g_pcnt[i]; }
    out[0] = (c > 0) ? (s / (float)c) : 0.0f;
}

// ---------------------------------------------------------------------------
extern "C" void kernel_launch(void* const* d_in, const int* in_sizes, int n_in,
                              void* d_out, int out_size) {
    const float* emb = (const float*)d_in[0];
    const int* labels = (const int*)d_in[1];
    float* out = (float*)d_out;

    init_kernel<<<1, 128>>>();
    normalize_kernel<<<NROWS, 128>>>(emb, labels);
    gram_tc_kernel<<<NTRI, 256>>>(labels);
    finalize1_kernel<<<NFB, 256>>>(labels);
    finalize2_kernel<<<1, 1>>>(out);
}

// round 9
// speedup vs baseline: 6.7737x; 1.1487x over previous
#include <cuda_runtime.h>
#include <math.h>
#include <stdint.h>

#define NROWS 4096
#define DIM   512
#define MARGIN 0.3f
#define FLT_BIG 3.402823466e+38f

#define BM 128
#define BN 128
#define BK 32
#define SST 36          // smem row stride (floats): conflict-free frag reads
#define NCH (DIM / BK)  // 16 k-chunks
#define NTILE (NROWS / BM)              // 32
#define NTRI  (NTILE * (NTILE + 1) / 2) // 528 upper-triangular tiles
#define NFB 16          // finalize blocks
#define SMEM_BYTES (2 * 2 * BM * SST * 4)   // 2 ops x 2 stages = 73728 B

// Scratch (device globals: no allocation allowed)
__device__ float    g_e[NROWS * DIM];   // normalized, tf32-rounded embeddings
__device__ unsigned g_ap_bits[NROWS];   // min-gram-over-positives (monotone key)
__device__ unsigned g_an_bits[NROWS];   // max-gram-over-negatives (monotone key)
__device__ float    g_psum[NFB];
__device__ int      g_pcnt[NFB];
__device__ int      g_ticket;           // zero-init; last finalize block resets

#define AP_IDENT 0xFFFFFFFFu   // identity for key-min (only NaN maps here)
#define AN_IDENT 0u            // identity for key-max (only NaN maps here)

// monotone float <-> uint key (order-preserving for all finite floats)
__device__ __forceinline__ unsigned fkey(float x) {
    unsigned b = __float_as_uint(x);
    return (b & 0x80000000u) ? ~b : (b | 0x80000000u);
}
__device__ __forceinline__ float funkey(unsigned k) {
    unsigned b = (k & 0x80000000u) ? (k ^ 0x80000000u) : ~k;
    return __uint_as_float(b);
}

// ---------------------------------------------------------------------------
// normalize + tf32 round + per-row reduction-buffer reset.
// ---------------------------------------------------------------------------
__device__ __forceinline__ float to_tf32(float x) {
    float r;
    asm("cvt.rna.tf32.f32 %0, %1;" : "=f"(r) : "f"(x));
    return r;
}

__global__ void normalize_kernel(const float* __restrict__ emb) {
    int row = blockIdx.x;
    int t = threadIdx.x;  // 0..127
    if (t == 0) {
        g_ap_bits[row] = AP_IDENT;
        g_an_bits[row] = AN_IDENT;
    }
    const float4* in = (const float4*)(emb + (size_t)row * DIM);
    float4 v = in[t];
    float ss = v.x * v.x + v.y * v.y + v.z * v.z + v.w * v.w;
    #pragma unroll
    for (int o = 16; o > 0; o >>= 1) ss += __shfl_xor_sync(0xffffffffu, ss, o);
    __shared__ float sw[4];
    __shared__ float sinv;
    if ((t & 31) == 0) sw[t >> 5] = ss;
    __syncthreads();
    if (t == 0) {
        float tot = sw[0] + sw[1] + sw[2] + sw[3];
        sinv = 1.0f / fmaxf(sqrtf(tot), 1e-12f);
    }
    __syncthreads();
    float inv = sinv;
    float4 o4 = make_float4(to_tf32(v.x * inv), to_tf32(v.y * inv),
                            to_tf32(v.z * inv), to_tf32(v.w * inv));
    ((float4*)(g_e + (size_t)row * DIM))[t] = o4;
}

// ---------------------------------------------------------------------------
// Tensor-core gram, upper-triangular tiles, BK=32 + 2-stage cp.async,
// gram-space dual-axis epilogue (hardest-pos = min gram, hardest-neg = max).
// ---------------------------------------------------------------------------
#define MMA_TF32(cc, aa, bb)                                                   \
    asm volatile(                                                              \
        "mma.sync.aligned.m16n8k8.row.col.f32.tf32.tf32.f32 "                  \
        "{%0,%1,%2,%3}, {%4,%5,%6,%7}, {%8,%9}, {%0,%1,%2,%3};"                \
        : "+f"((cc)[0]), "+f"((cc)[1]), "+f"((cc)[2]), "+f"((cc)[3])           \
        : "r"((aa)[0]), "r"((aa)[1]), "r"((aa)[2]), "r"((aa)[3]),              \
          "r"((bb)[0]), "r"((bb)[1]))

#define CP16(dst, src)                                                         \
    asm volatile("cp.async.cg.shared.global [%0], [%1], 16;"                   \
                 :: "r"(dst), "l"(src))
#define CP_COMMIT() asm volatile("cp.async.commit_group;")
#define CP_WAIT1()  asm volatile("cp.async.wait_group 1;")
#define CP_WAIT0()  asm volatile("cp.async.wait_group 0;")

__device__ __forceinline__ int tri_offset(int bi) {
    return bi * NTILE - bi * (bi - 1) / 2;
}

extern __shared__ float dynsmem[];

__global__ __launch_bounds__(256, 2)
void gram_tc_kernel(const int* __restrict__ labels) {
    __shared__ int sli[BM];
    __shared__ int slj[BN];

    // decode linear tile id -> (bi, bj), bi <= bj
    const int u = blockIdx.x;
    int bi = (int)((65.0f - sqrtf(65.0f * 65.0f - 8.0f * (float)u)) * 0.5f);
    while (tri_offset(bi) > u) bi--;
    while (tri_offset(bi + 1) <= u) bi++;
    const int bj = bi + (u - tri_offset(bi));

    const int tid = threadIdx.x;
    const int i0 = bi * BM;
    const int j0 = bj * BN;
    const bool offdiag = (bi != bj);

    if (tid < 128) sli[tid] = labels[i0 + tid];
    else           slj[tid - 128] = labels[j0 + (tid - 128)];

    const int warp = tid >> 5;
    const int lane = tid & 31;
    const int wm = warp >> 2;      // 0..1 -> 64-row band
    const int wn = warp & 3;       // 0..3 -> 32-col band
    const int g  = lane >> 2;      // 0..7
    const int t  = lane & 3;       // 0..3

    // staging map: thread covers rows {r, r+32, r+64, r+96}, 16B at col c4
    const int r  = tid >> 3;       // 0..31
    const int c4 = (tid & 7) * 4;  // 0,4,...,28
    const float* gA = g_e + (size_t)(i0 + r) * DIM + c4;
    const float* gB = g_e + (size_t)(j0 + r) * DIM + c4;

    // dynamic smem layout: [A stage0][A stage1][B stage0][B stage1]
    float* Abase = dynsmem;
    float* Bbase = dynsmem + 2 * BM * SST;
    const uint32_t sA0 = (uint32_t)__cvta_generic_to_shared(Abase) +
                         (uint32_t)(r * SST + c4) * 4u;
    const uint32_t sB0 = (uint32_t)__cvta_generic_to_shared(Bbase) +
                         (uint32_t)(r * SST + c4) * 4u;
    const uint32_t STAGE = (uint32_t)(BM * SST) * 4u;
    const uint32_t ROW32 = (uint32_t)(32 * SST) * 4u;
    const size_t   G32   = (size_t)32 * DIM;

    float c[4][4][4];
    #pragma unroll
    for (int mt = 0; mt < 4; mt++)
        #pragma unroll
        for (int nt = 0; nt < 4; nt++)
            #pragma unroll
            for (int e = 0; e < 4; e++) c[mt][nt][e] = 0.0f;

    // prologue: prefetch chunk 0 into stage 0
    #pragma unroll
    for (int h = 0; h < 4; h++) {
        CP16(sA0 + h * ROW32, gA + h * G32);
        CP16(sB0 + h * ROW32, gB + h * G32);
    }
    CP_COMMIT();

    for (int ch = 0; ch < NCH; ch++) {
        const int s = ch & 1;
        if (ch + 1 < NCH) {
            const uint32_t so = ((ch + 1) & 1) ? STAGE : 0u;
            const int kc = (ch + 1) * BK;
            #pragma unroll
            for (int h = 0; h < 4; h++) {
                CP16(sA0 + so + h * ROW32, gA + h * G32 + kc);
                CP16(sB0 + so + h * ROW32, gB + h * G32 + kc);
            }
            CP_COMMIT();
            CP_WAIT1();
        } else {
            CP_WAIT0();
        }
        __syncthreads();

        const float* As = Abase + s * BM * SST;
        const float* Bs = Bbase + s * BM * SST;
        #pragma unroll
        for (int ks = 0; ks < 4; ks++) {
            const int kb = ks * 8;
            uint32_t a[4][4], b[4][2];
            #pragma unroll
            for (int mt = 0; mt < 4; mt++) {
                const int rr = wm * 64 + mt * 16 + g;
                a[mt][0] = __float_as_uint(As[rr * SST       + kb + t    ]);
                a[mt][1] = __float_as_uint(As[(rr + 8) * SST + kb + t    ]);
                a[mt][2] = __float_as_uint(As[rr * SST       + kb + t + 4]);
                a[mt][3] = __float_as_uint(As[(rr + 8) * SST + kb + t + 4]);
            }
            #pragma unroll
            for (int nt = 0; nt < 4; nt++) {
                const int rn = wn * 32 + nt * 8 + g;
                b[nt][0] = __float_as_uint(Bs[rn * SST + kb + t    ]);
                b[nt][1] = __float_as_uint(Bs[rn * SST + kb + t + 4]);
            }
            #pragma unroll
            for (int mt = 0; mt < 4; mt++)
                #pragma unroll
                for (int nt = 0; nt < 4; nt++)
                    MMA_TF32(c[mt][nt], a[mt], b[nt]);
        }
        __syncthreads();   // protect stage s before chunk ch+2 overwrites it
    }

    // -------- epilogue (gram space: pos -> min gram, neg -> max gram) --------
    // C frag layout: e=0,1 -> row g, cols 2t,2t+1 ; e=2,3 -> row g+8
    #pragma unroll
    for (int mt = 0; mt < 4; mt++) {
        const int lr0 = wm * 64 + mt * 16 + g;
        const int lr1 = lr0 + 8;
        const int ig0 = i0 + lr0, ig1 = i0 + lr1;
        const int li0 = sli[lr0], li1 = sli[lr1];
        float gp0 = FLT_BIG, gn0 = -FLT_BIG;
        float gp1 = FLT_BIG, gn1 = -FLT_BIG;
        #pragma unroll
        for (int nt = 0; nt < 4; nt++) {
            #pragma unroll
            for (int e = 0; e < 2; e++) {
                const int ljl = wn * 32 + nt * 8 + 2 * t + e;
                const int jg = j0 + ljl;
                const int lj = slj[ljl];
                float v0 = c[mt][nt][e];
                float v1 = c[mt][nt][2 + e];
                if (li0 == lj) { if (ig0 != jg) gp0 = fminf(gp0, v0); }
                else           gn0 = fmaxf(gn0, v0);
                if (li1 == lj) { if (ig1 != jg) gp1 = fminf(gp1, v1); }
                else           gn1 = fmaxf(gn1, v1);
            }
        }
        #pragma unroll
        for (int off = 1; off < 4; off <<= 1) {
            gp0 = fminf(gp0, __shfl_xor_sync(0xffffffffu, gp0, off, 4));
            gn0 = fmaxf(gn0, __shfl_xor_sync(0xffffffffu, gn0, off, 4));
            gp1 = fminf(gp1, __shfl_xor_sync(0xffffffffu, gp1, off, 4));
            gn1 = fmaxf(gn1, __shfl_xor_sync(0xffffffffu, gn1, off, 4));
        }
        if (t == 0) {
            if (gp0 <  FLT_BIG) atomicMin(&g_ap_bits[ig0], fkey(gp0));
            if (gn0 > -FLT_BIG) atomicMax(&g_an_bits[ig0], fkey(gn0));
            if (gp1 <  FLT_BIG) atomicMin(&g_ap_bits[ig1], fkey(gp1));
            if (gn1 > -FLT_BIG) atomicMax(&g_an_bits[ig1], fkey(gn1));
        }
    }

    // Column pass via symmetry (off-diagonal tiles; i/j ranges disjoint)
    if (offdiag) {
        #pragma unroll
        for (int nt = 0; nt < 4; nt++) {
            #pragma unroll
            for (int e = 0; e < 2; e++) {
                const int ljl = wn * 32 + nt * 8 + 2 * t + e;
                const int lj = slj[ljl];
                float gp = FLT_BIG, gn = -FLT_BIG;
                #pragma unroll
                for (int mt = 0; mt < 4; mt++) {
                    const int lr0 = wm * 64 + mt * 16 + g;
                    const int li0 = sli[lr0], li1 = sli[lr0 + 8];
                    float v0 = c[mt][nt][e];
                    float v1 = c[mt][nt][2 + e];
                    if (li0 == lj) gp = fminf(gp, v0); else gn = fmaxf(gn, v0);
                    if (li1 == lj) gp = fminf(gp, v1); else gn = fmaxf(gn, v1);
                }
                #pragma unroll
                for (int off = 4; off < 32; off <<= 1) {
                    gp = fminf(gp, __shfl_xor_sync(0xffffffffu, gp, off, 32));
                    gn = fmaxf(gn, __shfl_xor_sync(0xffffffffu, gn, off, 32));
                }
                if (lane < 4) {   // g == 0 lanes hold the result
                    const int jg = j0 + ljl;
                    if (gp <  FLT_BIG) atomicMin(&g_ap_bits[jg], fkey(gp));
                    if (gn > -FLT_BIG) atomicMax(&g_an_bits[jg], fkey(gn));
                }
            }
        }
    }
}

// ---------------------------------------------------------------------------
// finalize: 16 blocks, 1 row/thread. Validity = both reduction keys changed
// from identity (positive seen && negative seen). Last block (ticket) sums
// the 16 fixed partials -> deterministic.
// ---------------------------------------------------------------------------
__global__ void finalize_kernel(float* __restrict__ out) {
    const int tid = threadIdx.x;
    const int i = blockIdx.x * 256 + tid;
    unsigned apk = g_ap_bits[i];
    unsigned ank = g_an_bits[i];
    float loss = 0.0f;
    int valid = 0;
    if (apk != AP_IDENT && ank != AN_IDENT) {
        float gmin = funkey(apk);   // min gram over positives
        float gmax = funkey(ank);   // max gram over negatives
        float ap = sqrtf(fmaxf(2.0f - 2.0f * gmin, 0.0f));
        float an = sqrtf(fmaxf(2.0f - 2.0f * gmax, 0.0f));
        loss = fmaxf(ap - an + MARGIN, 0.0f);
        valid = 1;
    }
    __shared__ float ssum[256];
    __shared__ int   scnt[256];
    ssum[tid] = loss; scnt[tid] = valid;
    __syncthreads();
    for (int s = 128; s > 0; s >>= 1) {
        if (tid < s) { ssum[tid] += ssum[tid + s]; scnt[tid] += scnt[tid + s]; }
        __syncthreads();
    }
    __shared__ bool last;
    if (tid == 0) {
        g_psum[blockIdx.x] = ssum[0];
        g_pcnt[blockIdx.x] = scnt[0];
        __threadfence();
        last = (atomicAdd(&g_ticket, 1) == NFB - 1);
    }
    __syncthreads();
    if (last && tid == 0) {
        float s = 0.0f;
        int c = 0;
        #pragma unroll
        for (int b = 0; b < NFB; b++) { s += g_psum[b]; c += g_pcnt[b]; }
        out[0] = (c > 0) ? (s / (float)c) : 0.0f;
        g_ticket = 0;   // reset for next graph replay
    }
}

// ---------------------------------------------------------------------------
extern "C" void kernel_launch(void* const* d_in, const int* in_sizes, int n_in,
                              void* d_out, int out_size) {
    const float* emb = (const float*)d_in[0];
    const int* labels = (const int*)d_in[1];
    float* out = (float*)d_out;

    cudaFuncSetAttribute(gram_tc_kernel,
                         cudaFuncAttributeMaxDynamicSharedMemorySize, SMEM_BYTES);

    normalize_kernel<<<NROWS, 128>>>(emb);
    gram_tc_kernel<<<NTRI, 256, SMEM_BYTES>>>(labels);
    finalize_kernel<<<NFB, 256>>>(out);
}

// round 12
// speedup vs baseline: 10.6912x; 1.5783x over previous
#include <cuda_runtime.h>
#include <cuda_fp16.h>
#include <math.h>
#include <stdint.h>

#define NROWS 4096
#define DIM   512
#define MARGIN 0.3f
#define FLT_BIG 3.402823466e+38f

#define BM 128
#define BN 128
#define BKH 64          // k per chunk, in halves (128 bytes per row)
#define SSTH 72         // smem row stride in halves (144 B); 36 words -> 4g+t banks
#define SSTW (SSTH / 2) // 36 words
#define NCH (DIM / BKH) // 8 k-chunks
#define NTILE (NROWS / BM)              // 32
#define NTRI  (NTILE * (NTILE + 1) / 2) // 528 upper-triangular tiles
#define NFB 16          // finalize blocks
#define SMEM_BYTES (2 * 2 * BM * SSTH * 2)   // 2 ops x 2 stages x 128 x 144B = 73728

// Scratch (device globals: no allocation allowed)
__device__ __half   g_e[NROWS * DIM];   // normalized fp16 embeddings
__device__ unsigned g_ap_bits[NROWS];   // min-gram-over-positives (monotone key)
__device__ unsigned g_an_bits[NROWS];   // max-gram-over-negatives (monotone key)
__device__ float    g_psum[NFB];
__device__ int      g_pcnt[NFB];
__device__ int      g_ticket;           // zero-init; last finalize block resets

#define AP_IDENT 0xFFFFFFFFu   // identity for key-min (only NaN maps here)
#define AN_IDENT 0u            // identity for key-max (only NaN maps here)

// monotone float <-> uint key (order-preserving for all finite floats)
__device__ __forceinline__ unsigned fkey(float x) {
    unsigned b = __float_as_uint(x);
    return (b & 0x80000000u) ? ~b : (b | 0x80000000u);
}
__device__ __forceinline__ float funkey(unsigned k) {
    unsigned b = (k & 0x80000000u) ? (k ^ 0x80000000u) : ~k;
    return __uint_as_float(b);
}

__device__ __forceinline__ uint32_t h2_as_u32(__half2 h) {
    return *reinterpret_cast<uint32_t*>(&h);
}

// ---------------------------------------------------------------------------
// normalize -> fp16 + per-row reduction-buffer reset.
// One block per row, 128 threads, float4 per thread.
// ---------------------------------------------------------------------------
__global__ void normalize_kernel(const float* __restrict__ emb) {
    int row = blockIdx.x;
    int t = threadIdx.x;  // 0..127
    if (t == 0) {
        g_ap_bits[row] = AP_IDENT;
        g_an_bits[row] = AN_IDENT;
    }
    const float4* in = (const float4*)(emb + (size_t)row * DIM);
    float4 v = in[t];
    float ss = v.x * v.x + v.y * v.y + v.z * v.z + v.w * v.w;
    #pragma unroll
    for (int o = 16; o > 0; o >>= 1) ss += __shfl_xor_sync(0xffffffffu, ss, o);
    __shared__ float sw[4];
    __shared__ float sinv;
    if ((t & 31) == 0) sw[t >> 5] = ss;
    __syncthreads();
    if (t == 0) {
        float tot = sw[0] + sw[1] + sw[2] + sw[3];
        sinv = 1.0f / fmaxf(sqrtf(tot), 1e-12f);
    }
    __syncthreads();
    float inv = sinv;
    uint2 pack;
    pack.x = h2_as_u32(__floats2half2_rn(v.x * inv, v.y * inv));
    pack.y = h2_as_u32(__floats2half2_rn(v.z * inv, v.w * inv));
    ((uint2*)(g_e + (size_t)row * DIM))[t] = pack;
}

// ---------------------------------------------------------------------------
// Tensor-core gram (fp16 m16n8k16, f32 accum), upper-triangular tiles,
// BK=64 halves + 2-stage cp.async, gram-space dual-axis epilogue.
// ---------------------------------------------------------------------------
#define MMA_F16(cc, aa, bb)                                                    \
    asm volatile(                                                              \
        "mma.sync.aligned.m16n8k16.row.col.f32.f16.f16.f32 "                   \
        "{%0,%1,%2,%3}, {%4,%5,%6,%7}, {%8,%9}, {%0,%1,%2,%3};"                \
        : "+f"((cc)[0]), "+f"((cc)[1]), "+f"((cc)[2]), "+f"((cc)[3])           \
        : "r"((aa)[0]), "r"((aa)[1]), "r"((aa)[2]), "r"((aa)[3]),              \
          "r"((bb)[0]), "r"((bb)[1]))

#define CP16(dst, src)                                                         \
    asm volatile("cp.async.cg.shared.global [%0], [%1], 16;"                   \
                 :: "r"(dst), "l"(src))
#define CP_COMMIT() asm volatile("cp.async.commit_group;")
#define CP_WAIT1()  asm volatile("cp.async.wait_group 1;")
#define CP_WAIT0()  asm volatile("cp.async.wait_group 0;")

__device__ __forceinline__ int tri_offset(int bi) {
    return bi * NTILE - bi * (bi - 1) / 2;
}

extern __shared__ __half dynsmem[];

__global__ __launch_bounds__(256, 2)
void gram_tc_kernel(const int* __restrict__ labels) {
    __shared__ int sli[BM];
    __shared__ int slj[BN];

    // decode linear tile id -> (bi, bj), bi <= bj
    const int u = blockIdx.x;
    int bi = (int)((65.0f - sqrtf(65.0f * 65.0f - 8.0f * (float)u)) * 0.5f);
    while (tri_offset(bi) > u) bi--;
    while (tri_offset(bi + 1) <= u) bi++;
    const int bj = bi + (u - tri_offset(bi));

    const int tid = threadIdx.x;
    const int i0 = bi * BM;
    const int j0 = bj * BN;
    const bool offdiag = (bi != bj);

    if (tid < 128) sli[tid] = labels[i0 + tid];
    else           slj[tid - 128] = labels[j0 + (tid - 128)];

    const int warp = tid >> 5;
    const int lane = tid & 31;
    const int wm = warp >> 2;      // 0..1 -> 64-row band
    const int wn = warp & 3;       // 0..3 -> 32-col band
    const int g  = lane >> 2;      // 0..7
    const int t  = lane & 3;       // 0..3

    // staging map: thread covers rows {r, r+32, r+64, r+96}, 16B (8 halves)
    const int r  = tid >> 3;       // 0..31
    const int c8 = (tid & 7) * 8;  // 0,8,...,56 (halves)
    const __half* gA = g_e + (size_t)(i0 + r) * DIM + c8;
    const __half* gB = g_e + (size_t)(j0 + r) * DIM + c8;

    // dynamic smem layout: [A stage0][A stage1][B stage0][B stage1]
    __half* Abase = dynsmem;
    __half* Bbase = dynsmem + 2 * BM * SSTH;
    const uint32_t sA0 = (uint32_t)__cvta_generic_to_shared(Abase) +
                         (uint32_t)(r * SSTH + c8) * 2u;
    const uint32_t sB0 = (uint32_t)__cvta_generic_to_shared(Bbase) +
                         (uint32_t)(r * SSTH + c8) * 2u;
    const uint32_t STAGE = (uint32_t)(BM * SSTH) * 2u;   // bytes per stage
    const uint32_t ROW32 = (uint32_t)(32 * SSTH) * 2u;   // +32 rows, bytes
    const size_t   G32   = (size_t)32 * DIM;             // +32 rows, halves

    float c[4][4][4];
    #pragma unroll
    for (int mt = 0; mt < 4; mt++)
        #pragma unroll
        for (int nt = 0; nt < 4; nt++)
            #pragma unroll
            for (int e = 0; e < 4; e++) c[mt][nt][e] = 0.0f;

    // prologue: prefetch chunk 0 into stage 0
    #pragma unroll
    for (int h = 0; h < 4; h++) {
        CP16(sA0 + h * ROW32, gA + h * G32);
        CP16(sB0 + h * ROW32, gB + h * G32);
    }
    CP_COMMIT();

    for (int ch = 0; ch < NCH; ch++) {
        const int s = ch & 1;
        if (ch + 1 < NCH) {
            const uint32_t so = ((ch + 1) & 1) ? STAGE : 0u;
            const int kc = (ch + 1) * BKH;
            #pragma unroll
            for (int h = 0; h < 4; h++) {
                CP16(sA0 + so + h * ROW32, gA + h * G32 + kc);
                CP16(sB0 + so + h * ROW32, gB + h * G32 + kc);
            }
            CP_COMMIT();
            CP_WAIT1();
        } else {
            CP_WAIT0();
        }
        __syncthreads();

        const uint32_t* As32 = (const uint32_t*)(Abase + s * BM * SSTH);
        const uint32_t* Bs32 = (const uint32_t*)(Bbase + s * BM * SSTH);
        #pragma unroll
        for (int ks = 0; ks < 4; ks++) {        // 4 x k16 per 64-half chunk
            const int kb2 = ks * 8;             // k offset in words
            uint32_t a[4][4], b[4][2];
            #pragma unroll
            for (int mt = 0; mt < 4; mt++) {
                const int rr = wm * 64 + mt * 16 + g;
                // reg0: row rr,   k=2t,2t+1 ; reg1: row rr+8, same
                // reg2: row rr,   k=2t+8,+9 ; reg3: row rr+8, same
                a[mt][0] = As32[rr * SSTW       + kb2 + t    ];
                a[mt][1] = As32[(rr + 8) * SSTW + kb2 + t    ];
                a[mt][2] = As32[rr * SSTW       + kb2 + 4 + t];
                a[mt][3] = As32[(rr + 8) * SSTW + kb2 + 4 + t];
            }
            #pragma unroll
            for (int nt = 0; nt < 4; nt++) {
                const int rn = wn * 32 + nt * 8 + g;
                b[nt][0] = Bs32[rn * SSTW + kb2 + t    ];
                b[nt][1] = Bs32[rn * SSTW + kb2 + 4 + t];
            }
            #pragma unroll
            for (int mt = 0; mt < 4; mt++)
                #pragma unroll
                for (int nt = 0; nt < 4; nt++)
                    MMA_F16(c[mt][nt], a[mt], b[nt]);
        }
        __syncthreads();   // protect stage s before chunk ch+2 overwrites it
    }

    // -------- epilogue (gram space: pos -> min gram, neg -> max gram) --------
    // C frag layout: e=0,1 -> row g, cols 2t,2t+1 ; e=2,3 -> row g+8
    #pragma unroll
    for (int mt = 0; mt < 4; mt++) {
        const int lr0 = wm * 64 + mt * 16 + g;
        const int lr1 = lr0 + 8;
        const int ig0 = i0 + lr0, ig1 = i0 + lr1;
        const int li0 = sli[lr0], li1 = sli[lr1];
        float gp0 = FLT_BIG, gn0 = -FLT_BIG;
        float gp1 = FLT_BIG, gn1 = -FLT_BIG;
        #pragma unroll
        for (int nt = 0; nt < 4; nt++) {
            #pragma unroll
            for (int e = 0; e < 2; e++) {
                const int ljl = wn * 32 + nt * 8 + 2 * t + e;
                const int jg = j0 + ljl;
                const int lj = slj[ljl];
                float v0 = c[mt][nt][e];
                float v1 = c[mt][nt][2 + e];
                if (li0 == lj) { if (ig0 != jg) gp0 = fminf(gp0, v0); }
                else           gn0 = fmaxf(gn0, v0);
                if (li1 == lj) { if (ig1 != jg) gp1 = fminf(gp1, v1); }
                else           gn1 = fmaxf(gn1, v1);
            }
        }
        #pragma unroll
        for (int off = 1; off < 4; off <<= 1) {
            gp0 = fminf(gp0, __shfl_xor_sync(0xffffffffu, gp0, off, 4));
            gn0 = fmaxf(gn0, __shfl_xor_sync(0xffffffffu, gn0, off, 4));
            gp1 = fminf(gp1, __shfl_xor_sync(0xffffffffu, gp1, off, 4));
            gn1 = fmaxf(gn1, __shfl_xor_sync(0xffffffffu, gn1, off, 4));
        }
        if (t == 0) {
            if (gp0 <  FLT_BIG) atomicMin(&g_ap_bits[ig0], fkey(gp0));
            if (gn0 > -FLT_BIG) atomicMax(&g_an_bits[ig0], fkey(gn0));
            if (gp1 <  FLT_BIG) atomicMin(&g_ap_bits[ig1], fkey(gp1));
            if (gn1 > -FLT_BIG) atomicMax(&g_an_bits[ig1], fkey(gn1));
        }
    }

    // Column pass via symmetry (off-diagonal tiles; i/j ranges disjoint)
    if (offdiag) {
        #pragma unroll
        for (int nt = 0; nt < 4; nt++) {
            #pragma unroll
            for (int e = 0; e < 2; e++) {
                const int ljl = wn * 32 + nt * 8 + 2 * t + e;
                const int lj = slj[ljl];
                float gp = FLT_BIG, gn = -FLT_BIG;
                #pragma unroll
                for (int mt = 0; mt < 4; mt++) {
                    const int lr0 = wm * 64 + mt * 16 + g;
                    const int li0 = sli[lr0], li1 = sli[lr0 + 8];
                    float v0 = c[mt][nt][e];
                    float v1 = c[mt][nt][2 + e];
                    if (li0 == lj) gp = fminf(gp, v0); else gn = fmaxf(gn, v0);
                    if (li1 == lj) gp = fminf(gp, v1); else gn = fmaxf(gn, v1);
                }
                #pragma unroll
                for (int off = 4; off < 32; off <<= 1) {
                    gp = fminf(gp, __shfl_xor_sync(0xffffffffu, gp, off, 32));
                    gn = fmaxf(gn, __shfl_xor_sync(0xffffffffu, gn, off, 32));
                }
                if (lane < 4) {   // g == 0 lanes hold the result
                    const int jg = j0 + ljl;
                    if (gp <  FLT_BIG) atomicMin(&g_ap_bits[jg], fkey(gp));
                    if (gn > -FLT_BIG) atomicMax(&g_an_bits[jg], fkey(gn));
                }
            }
        }
    }
}

// ---------------------------------------------------------------------------
// finalize: 16 blocks, 1 row/thread. Validity = both reduction keys changed
// from identity. Last block (ticket) sums the 16 fixed partials.
// ---------------------------------------------------------------------------
__global__ void finalize_kernel(float* __restrict__ out) {
    const int tid = threadIdx.x;
    const int i = blockIdx.x * 256 + tid;
    unsigned apk = g_ap_bits[i];
    unsigned ank = g_an_bits[i];
    float loss = 0.0f;
    int valid = 0;
    if (apk != AP_IDENT && ank != AN_IDENT) {
        float gmin = funkey(apk);   // min gram over positives
        float gmax = funkey(ank);   // max gram over negatives
        float ap = sqrtf(fmaxf(2.0f - 2.0f * gmin, 0.0f));
        float an = sqrtf(fmaxf(2.0f - 2.0f * gmax, 0.0f));
        loss = fmaxf(ap - an + MARGIN, 0.0f);
        valid = 1;
    }
    __shared__ float ssum[256];
    __shared__ int   scnt[256];
    ssum[tid] = loss; scnt[tid] = valid;
    __syncthreads();
    for (int s = 128; s > 0; s >>= 1) {
        if (tid < s) { ssum[tid] += ssum[tid + s]; scnt[tid] += scnt[tid + s]; }
        __syncthreads();
    }
    __shared__ bool last;
    if (tid == 0) {
        g_psum[blockIdx.x] = ssum[0];
        g_pcnt[blockIdx.x] = scnt[0];
        __threadfence();
        last = (atomicAdd(&g_ticket, 1) == NFB - 1);
    }
    __syncthreads();
    if (last && tid == 0) {
        float s = 0.0f;
        int c = 0;
        #pragma unroll
        for (int b = 0; b < NFB; b++) { s += g_psum[b]; c += g_pcnt[b]; }
        out[0] = (c > 0) ? (s / (float)c) : 0.0f;
        g_ticket = 0;   // reset for next graph replay
    }
}

// ---------------------------------------------------------------------------
extern "C" void kernel_launch(void* const* d_in, const int* in_sizes, int n_in,
                              void* d_out, int out_size) {
    const float* emb = (const float*)d_in[0];
    const int* labels = (const int*)d_in[1];
    float* out = (float*)d_out;

    cudaFuncSetAttribute(gram_tc_kernel,
                         cudaFuncAttributeMaxDynamicSharedMemorySize, SMEM_BYTES);

    normalize_kernel<<<NROWS, 128>>>(emb);
    gram_tc_kernel<<<NTRI, 256, SMEM_BYTES>>>(labels);
    finalize_kernel<<<NFB, 256>>>(out);
}

// round 13
// speedup vs baseline: 12.2016x; 1.1413x over previous
#include <cuda_runtime.h>
#include <cuda_fp16.h>
#include <math.h>
#include <stdint.h>

#define NROWS 4096
#define DIM   512
#define MARGIN 0.3f
#define FLT_BIG 3.402823466e+38f

#define BM 128
#define BN 128
#define BKH 64          // k per chunk, in halves (128 bytes per row)
#define SSTH 72         // smem row stride in halves (144 B); stride = 4 banks mod 32
#define SSTW (SSTH / 2) // 36 words
#define NCH (DIM / BKH) // 8 k-chunks
#define NTILE (NROWS / BM)              // 32
#define NTRI  (NTILE * (NTILE + 1) / 2) // 528 upper-triangular tiles
#define NFB 16          // finalize blocks
#define SMEM_BYTES (2 * 2 * BM * SSTH * 2)   // 2 ops x 2 stages x 128 x 144B = 73728

// Scratch (device globals: no allocation allowed)
__device__ __half   g_e[NROWS * DIM];   // normalized fp16 embeddings
__device__ unsigned g_ap_bits[NROWS];   // min-gram-over-positives (monotone key)
__device__ unsigned g_an_bits[NROWS];   // max-gram-over-negatives (monotone key)
__device__ float    g_psum[NFB];
__device__ int      g_pcnt[NFB];
__device__ int      g_ticket;           // zero-init; last finalize block resets

#define AP_IDENT 0xFFFFFFFFu   // identity for key-min (only NaN maps here)
#define AN_IDENT 0u            // identity for key-max (only NaN maps here)

// monotone float <-> uint key (order-preserving for all finite floats)
__device__ __forceinline__ unsigned fkey(float x) {
    unsigned b = __float_as_uint(x);
    return (b & 0x80000000u) ? ~b : (b | 0x80000000u);
}
__device__ __forceinline__ float funkey(unsigned k) {
    unsigned b = (k & 0x80000000u) ? (k ^ 0x80000000u) : ~k;
    return __uint_as_float(b);
}

__device__ __forceinline__ uint32_t h2_as_u32(__half2 h) {
    return *reinterpret_cast<uint32_t*>(&h);
}

// ---------------------------------------------------------------------------
// normalize -> fp16 + per-row reduction-buffer reset.
// Warp-per-row: 1024 blocks x 128 threads (4 warps), no block barrier.
// ---------------------------------------------------------------------------
__global__ void normalize_kernel(const float* __restrict__ emb) {
    const int w = threadIdx.x >> 5;
    const int lane = threadIdx.x & 31;
    const int row = blockIdx.x * 4 + w;
    if (lane == 0) {
        g_ap_bits[row] = AP_IDENT;
        g_an_bits[row] = AN_IDENT;
    }
    const float4* in = (const float4*)(emb + (size_t)row * DIM);
    float4 v[4];
    float ss = 0.0f;
    #pragma unroll
    for (int i = 0; i < 4; i++) {
        v[i] = in[lane + 32 * i];
        ss += v[i].x * v[i].x + v[i].y * v[i].y + v[i].z * v[i].z + v[i].w * v[i].w;
    }
    #pragma unroll
    for (int o = 16; o > 0; o >>= 1) ss += __shfl_xor_sync(0xffffffffu, ss, o);
    const float inv = 1.0f / fmaxf(sqrtf(ss), 1e-12f);
    uint2* outp = (uint2*)(g_e + (size_t)row * DIM);
    #pragma unroll
    for (int i = 0; i < 4; i++) {
        uint2 pack;
        pack.x = h2_as_u32(__floats2half2_rn(v[i].x * inv, v[i].y * inv));
        pack.y = h2_as_u32(__floats2half2_rn(v[i].z * inv, v[i].w * inv));
        outp[lane + 32 * i] = pack;
    }
}

// ---------------------------------------------------------------------------
// Tensor-core gram (fp16 m16n8k16, f32 accum), upper-triangular tiles,
// BK=64 halves + 2-stage cp.async (1 barrier/chunk), ldmatrix frag loads,
// gram-space dual-axis epilogue.
// ---------------------------------------------------------------------------
#define MMA_F16(cc, aa, bb)                                                    \
    asm volatile(                                                              \
        "mma.sync.aligned.m16n8k16.row.col.f32.f16.f16.f32 "                   \
        "{%0,%1,%2,%3}, {%4,%5,%6,%7}, {%8,%9}, {%0,%1,%2,%3};"                \
        : "+f"((cc)[0]), "+f"((cc)[1]), "+f"((cc)[2]), "+f"((cc)[3])           \
        : "r"((aa)[0]), "r"((aa)[1]), "r"((aa)[2]), "r"((aa)[3]),              \
          "r"((bb)[0]), "r"((bb)[1]))

#define LDSM4(r0, r1, r2, r3, addr)                                            \
    asm volatile("ldmatrix.sync.aligned.m8n8.x4.shared.b16 {%0,%1,%2,%3}, [%4];" \
                 : "=r"(r0), "=r"(r1), "=r"(r2), "=r"(r3) : "r"(addr))

#define CP16(dst, src)                                                         \
    asm volatile("cp.async.cg.shared.global [%0], [%1], 16;"                   \
                 :: "r"(dst), "l"(src))
#define CP_COMMIT() asm volatile("cp.async.commit_group;")
#define CP_WAIT0()  asm volatile("cp.async.wait_group 0;")

__device__ __forceinline__ int tri_offset(int bi) {
    return bi * NTILE - bi * (bi - 1) / 2;
}

extern __shared__ __half dynsmem[];

__global__ __launch_bounds__(256, 2)
void gram_tc_kernel(const int* __restrict__ labels) {
    __shared__ int sli[BM];
    __shared__ int slj[BN];

    // decode linear tile id -> (bi, bj), bi <= bj
    const int u = blockIdx.x;
    int bi = (int)((65.0f - sqrtf(65.0f * 65.0f - 8.0f * (float)u)) * 0.5f);
    while (tri_offset(bi) > u) bi--;
    while (tri_offset(bi + 1) <= u) bi++;
    const int bj = bi + (u - tri_offset(bi));

    const int tid = threadIdx.x;
    const int i0 = bi * BM;
    const int j0 = bj * BN;
    const bool offdiag = (bi != bj);

    if (tid < 128) sli[tid] = labels[i0 + tid];
    else           slj[tid - 128] = labels[j0 + (tid - 128)];

    const int warp = tid >> 5;
    const int lane = tid & 31;
    const int wm = warp >> 2;      // 0..1 -> 64-row band
    const int wn = warp & 3;       // 0..3 -> 32-col band
    const int g  = lane >> 2;      // 0..7
    const int t  = lane & 3;       // 0..3

    // staging map: thread covers rows {r, r+32, r+64, r+96}, 16B (8 halves)
    const int r  = tid >> 3;       // 0..31
    const int c8 = (tid & 7) * 8;  // 0,8,...,56 (halves)
    const __half* gA = g_e + (size_t)(i0 + r) * DIM + c8;
    const __half* gB = g_e + (size_t)(j0 + r) * DIM + c8;

    // dynamic smem layout: [A stage0][A stage1][B stage0][B stage1]
    __half* Abase = dynsmem;
    __half* Bbase = dynsmem + 2 * BM * SSTH;
    const uint32_t smA = (uint32_t)__cvta_generic_to_shared(Abase);
    const uint32_t smB = (uint32_t)__cvta_generic_to_shared(Bbase);
    const uint32_t sA0 = smA + (uint32_t)(r * SSTH + c8) * 2u;
    const uint32_t sB0 = smB + (uint32_t)(r * SSTH + c8) * 2u;
    const uint32_t STAGE = (uint32_t)(BM * SSTH) * 2u;   // bytes per stage
    const uint32_t ROW32 = (uint32_t)(32 * SSTH) * 2u;   // +32 rows, bytes
    const size_t   G32   = (size_t)32 * DIM;             // +32 rows, halves

    // ldmatrix per-lane base addresses (bytes)
    // A tiles per mt: (rr,k0)(rr+8,k0)(rr,k4)(rr+8,k4); lanes 0-7/8-15/16-23/24-31
    // B tiles per pair p: (rn,k0)(rn,k4)(rn+8,k0)(rn+8,k4)
    const int tsel = lane >> 3;
    const int l8 = lane & 7;
    const uint32_t aAddr0 = smA +
        (uint32_t)(((wm * 64 + ((tsel & 1) << 3) + l8) * SSTW + ((tsel >> 1) << 2)) * 4);
    const uint32_t bAddr0 = smB +
        (uint32_t)(((wn * 32 + ((tsel >> 1) << 3) + l8) * SSTW + ((tsel & 1) << 2)) * 4);
    const uint32_t MT16 = (uint32_t)(16 * SSTW * 4);   // +16 rows, bytes

    float c[4][4][4];
    #pragma unroll
    for (int mt = 0; mt < 4; mt++)
        #pragma unroll
        for (int nt = 0; nt < 4; nt++)
            #pragma unroll
            for (int e = 0; e < 4; e++) c[mt][nt][e] = 0.0f;

    // prologue: prefetch chunk 0 into stage 0
    #pragma unroll
    for (int h = 0; h < 4; h++) {
        CP16(sA0 + h * ROW32, gA + h * G32);
        CP16(sB0 + h * ROW32, gB + h * G32);
    }
    CP_COMMIT();

    for (int ch = 0; ch < NCH; ch++) {
        const int s = ch & 1;
        CP_WAIT0();
        __syncthreads();   // stage-ch data visible + compute(ch-1) done everywhere

        if (ch + 1 < NCH) {
            const uint32_t so = ((ch + 1) & 1) ? STAGE : 0u;
            const int kc = (ch + 1) * BKH;
            #pragma unroll
            for (int h = 0; h < 4; h++) {
                CP16(sA0 + so + h * ROW32, gA + h * G32 + kc);
                CP16(sB0 + so + h * ROW32, gB + h * G32 + kc);
            }
            CP_COMMIT();
        }

        const uint32_t stA = aAddr0 + s * STAGE;
        const uint32_t stB = bAddr0 + s * STAGE;
        #pragma unroll
        for (int ks = 0; ks < 4; ks++) {        // 4 x k16 per 64-half chunk
            const uint32_t kOff = ks * 32;      // 8 words = 32 bytes
            uint32_t a[4][4], b[4][2];
            #pragma unroll
            for (int mt = 0; mt < 4; mt++)
                LDSM4(a[mt][0], a[mt][1], a[mt][2], a[mt][3],
                      stA + mt * MT16 + kOff);
            #pragma unroll
            for (int p = 0; p < 2; p++)
                LDSM4(b[2 * p][0], b[2 * p][1], b[2 * p + 1][0], b[2 * p + 1][1],
                      stB + p * MT16 + kOff);
            #pragma unroll
            for (int mt = 0; mt < 4; mt++)
                #pragma unroll
                for (int nt = 0; nt < 4; nt++)
                    MMA_F16(c[mt][nt], a[mt], b[nt]);
        }
    }

    // -------- epilogue (gram space: pos -> min gram, neg -> max gram) --------
    // C frag layout: e=0,1 -> row g, cols 2t,2t+1 ; e=2,3 -> row g+8
    #pragma unroll
    for (int mt = 0; mt < 4; mt++) {
        const int lr0 = wm * 64 + mt * 16 + g;
        const int lr1 = lr0 + 8;
        const int ig0 = i0 + lr0, ig1 = i0 + lr1;
        const int li0 = sli[lr0], li1 = sli[lr1];
        float gp0 = FLT_BIG, gn0 = -FLT_BIG;
        float gp1 = FLT_BIG, gn1 = -FLT_BIG;
        #pragma unroll
        for (int nt = 0; nt < 4; nt++) {
            #pragma unroll
            for (int e = 0; e < 2; e++) {
                const int ljl = wn * 32 + nt * 8 + 2 * t + e;
                const int jg = j0 + ljl;
                const int lj = slj[ljl];
                float v0 = c[mt][nt][e];
                float v1 = c[mt][nt][2 + e];
                if (li0 == lj) { if (ig0 != jg) gp0 = fminf(gp0, v0); }
                else           gn0 = fmaxf(gn0, v0);
                if (li1 == lj) { if (ig1 != jg) gp1 = fminf(gp1, v1); }
                else           gn1 = fmaxf(gn1, v1);
            }
        }
        #pragma unroll
        for (int off = 1; off < 4; off <<= 1) {
            gp0 = fminf(gp0, __shfl_xor_sync(0xffffffffu, gp0, off, 4));
            gn0 = fmaxf(gn0, __shfl_xor_sync(0xffffffffu, gn0, off, 4));
            gp1 = fminf(gp1, __shfl_xor_sync(0xffffffffu, gp1, off, 4));
            gn1 = fmaxf(gn1, __shfl_xor_sync(0xffffffffu, gn1, off, 4));
        }
        if (t == 0) {
            if (gp0 <  FLT_BIG) atomicMin(&g_ap_bits[ig0], fkey(gp0));
            if (gn0 > -FLT_BIG) atomicMax(&g_an_bits[ig0], fkey(gn0));
            if (gp1 <  FLT_BIG) atomicMin(&g_ap_bits[ig1], fkey(gp1));
            if (gn1 > -FLT_BIG) atomicMax(&g_an_bits[ig1], fkey(gn1));
        }
    }

    // Column pass via symmetry (off-diagonal tiles; i/j ranges disjoint)
    if (offdiag) {
        #pragma unroll
        for (int nt = 0; nt < 4; nt++) {
            #pragma unroll
            for (int e = 0; e < 2; e++) {
                const int ljl = wn * 32 + nt * 8 + 2 * t + e;
                const int lj = slj[ljl];
                float gp = FLT_BIG, gn = -FLT_BIG;
                #pragma unroll
                for (int mt = 0; mt < 4; mt++) {
                    const int lr0 = wm * 64 + mt * 16 + g;
                    const int li0 = sli[lr0], li1 = sli[lr0 + 8];
                    float v0 = c[mt][nt][e];
                    float v1 = c[mt][nt][2 + e];
                    if (li0 == lj) gp = fminf(gp, v0); else gn = fmaxf(gn, v0);
                    if (li1 == lj) gp = fminf(gp, v1); else gn = fmaxf(gn, v1);
                }
                #pragma unroll
                for (int off = 4; off < 32; off <<= 1) {
                    gp = fminf(gp, __shfl_xor_sync(0xffffffffu, gp, off, 32));
                    gn = fmaxf(gn, __shfl_xor_sync(0xffffffffu, gn, off, 32));
                }
                if (lane < 4) {   // g == 0 lanes hold the result
                    const int jg = j0 + ljl;
                    if (gp <  FLT_BIG) atomicMin(&g_ap_bits[jg], fkey(gp));
                    if (gn > -FLT_BIG) atomicMax(&g_an_bits[jg], fkey(gn));
                }
            }
        }
    }
}

// ---------------------------------------------------------------------------
// finalize: 16 blocks, 1 row/thread. Validity = both reduction keys changed
// from identity. Last block (ticket) sums the 16 fixed partials.
// ---------------------------------------------------------------------------
__global__ void finalize_kernel(float* __restrict__ out) {
    const int tid = threadIdx.x;
    const int i = blockIdx.x * 256 + tid;
    unsigned apk = g_ap_bits[i];
    unsigned ank = g_an_bits[i];
    float loss = 0.0f;
    int valid = 0;
    if (apk != AP_IDENT && ank != AN_IDENT) {
        float gmin = funkey(apk);   // min gram over positives
        float gmax = funkey(ank);   // max gram over negatives
        float ap = sqrtf(fmaxf(2.0f - 2.0f * gmin, 0.0f));
        float an = sqrtf(fmaxf(2.0f - 2.0f * gmax, 0.0f));
        loss = fmaxf(ap - an + MARGIN, 0.0f);
        valid = 1;
    }
    __shared__ float ssum[256];
    __shared__ int   scnt[256];
    ssum[tid] = loss; scnt[tid] = valid;
    __syncthreads();
    for (int s = 128; s > 0; s >>= 1) {
        if (tid < s) { ssum[tid] += ssum[tid + s]; scnt[tid] += scnt[tid + s]; }
        __syncthreads();
    }
    __shared__ bool last;
    if (tid == 0) {
        g_psum[blockIdx.x] = ssum[0];
        g_pcnt[blockIdx.x] = scnt[0];
        __threadfence();
        last = (atomicAdd(&g_ticket, 1) == NFB - 1);
    }
    __syncthreads();
    if (last && tid == 0) {
        float s = 0.0f;
        int c = 0;
        #pragma unroll
        for (int b = 0; b < NFB; b++) { s += g_psum[b]; c += g_pcnt[b]; }
        out[0] = (c > 0) ? (s / (float)c) : 0.0f;
        g_ticket = 0;   // reset for next graph replay
    }
}

// ---------------------------------------------------------------------------
extern "C" void kernel_launch(void* const* d_in, const int* in_sizes, int n_in,
                              void* d_out, int out_size) {
    const float* emb = (const float*)d_in[0];
    const int* labels = (const int*)d_in[1];
    float* out = (float*)d_out;

    cudaFuncSetAttribute(gram_tc_kernel,
                         cudaFuncAttributeMaxDynamicSharedMemorySize, SMEM_BYTES);

    normalize_kernel<<<NROWS / 4, 128>>>(emb);
    gram_tc_kernel<<<NTRI, 256, SMEM_BYTES>>>(labels);
    finalize_kernel<<<NFB, 256>>>(out);
}